// round 1
// baseline (speedup 1.0000x reference)
#include <cuda_runtime.h>
#include <math.h>

// Problem constants
#define BATCH   4
#define HH      64
#define WW      64
#define CIN     128
#define FILTERS 128
#define HEADS   8
#define HSIZE   16
#define K0      7
#define K1      7
#define KD      49
#define NPIX    (BATCH*HH*WW)      // 16384
#define NQKV    384                 // q|k|v concat

// Scratch: QKV[pix][384]  (q at +0, k at +128, v at +256)
__device__ float g_QKV[NPIX * NQKV];

// ---------------------------------------------------------------------------
// Kernel A: fused QKV projection.  C = X(16384x128) @ [Wq|Wk|Wv](128x384) + b
// ---------------------------------------------------------------------------
#define BM 64
#define BN 64
#define BK 32

__global__ __launch_bounds__(256)
void qkv_gemm_kernel(const float* __restrict__ X,
                     const float* __restrict__ Wq, const float* __restrict__ bq,
                     const float* __restrict__ Wk, const float* __restrict__ bk,
                     const float* __restrict__ Wv, const float* __restrict__ bv,
                     float* __restrict__ QKV)
{
    __shared__ float Xs[BK][BM];       // transposed X tile
    __shared__ float Ws[BK][BN];

    const int bm = blockIdx.x * BM;
    const int bn = blockIdx.y * BN;    // 0..320 step 64

    // select source weight/bias for this column block
    const float* W;  const float* bias;  int nn;
    if (bn < 128)       { W = Wq; bias = bq; nn = bn; }
    else if (bn < 256)  { W = Wk; bias = bk; nn = bn - 128; }
    else                { W = Wv; bias = bv; nn = bn - 256; }

    const int tx = threadIdx.x & 15;   // 0..15
    const int ty = threadIdx.x >> 4;   // 0..15

    float acc[4][4];
#pragma unroll
    for (int i = 0; i < 4; i++)
#pragma unroll
        for (int j = 0; j < 4; j++) acc[i][j] = 0.f;

    for (int k0 = 0; k0 < CIN; k0 += BK) {
        // load X tile (64 rows x 32 cols) transposed into Xs
#pragma unroll
        for (int i = threadIdx.x; i < BM * (BK/4); i += 256) {
            int r  = i / (BK/4);       // row in tile (pixel)
            int c4 = i % (BK/4);       // float4 column
            float4 v = *(const float4*)(X + (size_t)(bm + r) * CIN + k0 + c4*4);
            Xs[c4*4+0][r] = v.x;
            Xs[c4*4+1][r] = v.y;
            Xs[c4*4+2][r] = v.z;
            Xs[c4*4+3][r] = v.w;
        }
        // load W tile (32 rows x 64 cols)
#pragma unroll
        for (int i = threadIdx.x; i < BK * (BN/4); i += 256) {
            int r  = i / (BN/4);
            int c4 = i % (BN/4);
            *(float4*)&Ws[r][c4*4] =
                *(const float4*)(W + (size_t)(k0 + r) * FILTERS + nn + c4*4);
        }
        __syncthreads();

#pragma unroll
        for (int kk = 0; kk < BK; kk++) {
            float a[4], b[4];
#pragma unroll
            for (int i = 0; i < 4; i++) a[i] = Xs[kk][ty*4 + i];
#pragma unroll
            for (int j = 0; j < 4; j++) b[j] = Ws[kk][tx*4 + j];
#pragma unroll
            for (int i = 0; i < 4; i++)
#pragma unroll
                for (int j = 0; j < 4; j++) acc[i][j] += a[i] * b[j];
        }
        __syncthreads();
    }

    // epilogue: add bias, store float4
    float4 bv4;
    bv4.x = bias[nn + tx*4 + 0];
    bv4.y = bias[nn + tx*4 + 1];
    bv4.z = bias[nn + tx*4 + 2];
    bv4.w = bias[nn + tx*4 + 3];
#pragma unroll
    for (int i = 0; i < 4; i++) {
        int m = bm + ty*4 + i;
        float4 r;
        r.x = acc[i][0] + bv4.x;
        r.y = acc[i][1] + bv4.y;
        r.z = acc[i][2] + bv4.z;
        r.w = acc[i][3] + bv4.w;
        *(float4*)(QKV + (size_t)m * NQKV + bn + tx*4) = r;
    }
}

// ---------------------------------------------------------------------------
// Kernel B: per-(pixel,head) local attention over 7x7 window.
// key quirk: emb is added AFTER zero-pad, so OOB score = q . emb (kept in
// softmax); OOB v = 0.  emb term factors: depends only on di (h<4) or dj (h>=4)
// ---------------------------------------------------------------------------
__global__ __launch_bounds__(256)
void attn_kernel(const float* __restrict__ QKV,
                 const float* __restrict__ emb0,   // [64,7]
                 const float* __restrict__ emb1,   // [64,7]
                 float* __restrict__ out)
{
    const int t = blockIdx.x * blockDim.x + threadIdx.x;
    if (t >= NPIX * HEADS) return;
    const int h   = t & 7;
    const int pix = t >> 3;
    const int x   = pix & 63;
    const int y   = (pix >> 6) & 63;
    const int b   = pix >> 12;

    // load q[16]
    const float* qp = QKV + (size_t)pix * NQKV + h * HSIZE;
    float q[16];
#pragma unroll
    for (int d = 0; d < 16; d += 4) {
        float4 v = *(const float4*)(qp + d);
        q[d+0] = v.x; q[d+1] = v.y; q[d+2] = v.z; q[d+3] = v.w;
    }

    // qe[r] = sum_d q[d] * emb_row(h,d,r);  r = di for h<4 (emb0), dj for h>=4
    float qe[7];
    const bool use0 = (h < 4);
    const float* etab = use0 ? (emb0 + h * HSIZE * K0)
                             : (emb1 + (h * HSIZE - 64) * K1);
#pragma unroll
    for (int r = 0; r < 7; r++) {
        float s = 0.f;
#pragma unroll
        for (int d = 0; d < 16; d++) s += q[d] * etab[d * 7 + r];
        qe[r] = s;
    }

    // scores over 49 positions
    float scores[KD];
    float mx = -1e30f;
#pragma unroll
    for (int p = 0; p < KD; p++) {
        const int di = p / 7, dj = p % 7;
        const int yy = y + di - 3, xx = x + dj - 3;
        const bool inb = ((unsigned)yy < HH) && ((unsigned)xx < WW);
        float s = use0 ? qe[di] : qe[dj];
        if (inb) {
            const float* kp = QKV + ((size_t)(((b*HH)+yy)*WW + xx) * NQKV)
                                  + FILTERS + h * HSIZE;
#pragma unroll
            for (int d = 0; d < 16; d += 4) {
                float4 kv = *(const float4*)(kp + d);
                s += q[d+0]*kv.x + q[d+1]*kv.y + q[d+2]*kv.z + q[d+3]*kv.w;
            }
        }
        scores[p] = s;
        mx = fmaxf(mx, s);
    }

    // softmax
    float sum = 0.f;
#pragma unroll
    for (int p = 0; p < KD; p++) {
        float e = __expf(scores[p] - mx);
        scores[p] = e;
        sum += e;
    }
    const float inv = 1.f / sum;

    // weighted sum of v
    float o[16];
#pragma unroll
    for (int d = 0; d < 16; d++) o[d] = 0.f;
#pragma unroll
    for (int p = 0; p < KD; p++) {
        const int di = p / 7, dj = p % 7;
        const int yy = y + di - 3, xx = x + dj - 3;
        const bool inb = ((unsigned)yy < HH) && ((unsigned)xx < WW);
        if (inb) {
            const float w = scores[p];
            const float* vp = QKV + ((size_t)(((b*HH)+yy)*WW + xx) * NQKV)
                                  + 2*FILTERS + h * HSIZE;
#pragma unroll
            for (int d = 0; d < 16; d += 4) {
                float4 vv = *(const float4*)(vp + d);
                o[d+0] += w * vv.x; o[d+1] += w * vv.y;
                o[d+2] += w * vv.z; o[d+3] += w * vv.w;
            }
        }
    }

    float* op = out + (size_t)pix * FILTERS + h * HSIZE;
#pragma unroll
    for (int d = 0; d < 16; d += 4) {
        float4 r;
        r.x = o[d+0]*inv; r.y = o[d+1]*inv; r.z = o[d+2]*inv; r.w = o[d+3]*inv;
        *(float4*)(op + d) = r;
    }
}

// ---------------------------------------------------------------------------
extern "C" void kernel_launch(void* const* d_in, const int* in_sizes, int n_in,
                              void* d_out, int out_size)
{
    const float* x    = (const float*)d_in[0];
    const float* Wq   = (const float*)d_in[1];
    const float* bq   = (const float*)d_in[2];
    const float* Wk   = (const float*)d_in[3];
    const float* bk   = (const float*)d_in[4];
    const float* Wv   = (const float*)d_in[5];
    const float* bv   = (const float*)d_in[6];
    const float* emb0 = (const float*)d_in[7];
    const float* emb1 = (const float*)d_in[8];
    float* out = (float*)d_out;

    float* qkv = nullptr;
    cudaGetSymbolAddress((void**)&qkv, g_QKV);

    dim3 gg(NPIX / BM, NQKV / BN);   // (256, 6)
    qkv_gemm_kernel<<<gg, 256>>>(x, Wq, bq, Wk, bk, Wv, bv, qkv);

    const int total = NPIX * HEADS;  // 131072
    attn_kernel<<<(total + 255) / 256, 256>>>(qkv, emb0, emb1, out);
}

// round 2
// speedup vs baseline: 1.0887x; 1.0887x over previous
#include <cuda_runtime.h>
#include <math.h>

// Problem constants
#define BATCH   4
#define HH      64
#define WW      64
#define CIN     128
#define FILTERS 128
#define HEADS   8
#define HSIZE   16
#define K0      7
#define K1      7
#define KD      49
#define NPIX    (BATCH*HH*WW)      // 16384
#define NQKV    384                 // q|k|v concat

// Scratch: QKV[pix][384]  (q at +0, k at +128, v at +256)
__device__ float g_QKV[NPIX * NQKV];

// ---------------------------------------------------------------------------
// Kernel A: fused QKV projection.  C = X(16384x128) @ [Wq|Wk|Wv](128x384) + b
// ---------------------------------------------------------------------------
#define BM 64
#define BN 64
#define BK 32

__global__ __launch_bounds__(256)
void qkv_gemm_kernel(const float* __restrict__ X,
                     const float* __restrict__ Wq, const float* __restrict__ bq,
                     const float* __restrict__ Wk, const float* __restrict__ bk,
                     const float* __restrict__ Wv, const float* __restrict__ bv,
                     float* __restrict__ QKV)
{
    __shared__ float Xs[BK][BM];       // transposed X tile
    __shared__ float Ws[BK][BN];

    const int bm = blockIdx.x * BM;
    const int bn = blockIdx.y * BN;    // 0..320 step 64

    const float* W;  const float* bias;  int nn;
    if (bn < 128)       { W = Wq; bias = bq; nn = bn; }
    else if (bn < 256)  { W = Wk; bias = bk; nn = bn - 128; }
    else                { W = Wv; bias = bv; nn = bn - 256; }

    const int tx = threadIdx.x & 15;
    const int ty = threadIdx.x >> 4;

    float acc[4][4];
#pragma unroll
    for (int i = 0; i < 4; i++)
#pragma unroll
        for (int j = 0; j < 4; j++) acc[i][j] = 0.f;

    for (int k0 = 0; k0 < CIN; k0 += BK) {
#pragma unroll
        for (int i = threadIdx.x; i < BM * (BK/4); i += 256) {
            int r  = i / (BK/4);
            int c4 = i % (BK/4);
            float4 v = *(const float4*)(X + (size_t)(bm + r) * CIN + k0 + c4*4);
            Xs[c4*4+0][r] = v.x;
            Xs[c4*4+1][r] = v.y;
            Xs[c4*4+2][r] = v.z;
            Xs[c4*4+3][r] = v.w;
        }
#pragma unroll
        for (int i = threadIdx.x; i < BK * (BN/4); i += 256) {
            int r  = i / (BN/4);
            int c4 = i % (BN/4);
            *(float4*)&Ws[r][c4*4] =
                *(const float4*)(W + (size_t)(k0 + r) * FILTERS + nn + c4*4);
        }
        __syncthreads();

#pragma unroll
        for (int kk = 0; kk < BK; kk++) {
            float a[4], b[4];
#pragma unroll
            for (int i = 0; i < 4; i++) a[i] = Xs[kk][ty*4 + i];
#pragma unroll
            for (int j = 0; j < 4; j++) b[j] = Ws[kk][tx*4 + j];
#pragma unroll
            for (int i = 0; i < 4; i++)
#pragma unroll
                for (int j = 0; j < 4; j++) acc[i][j] += a[i] * b[j];
        }
        __syncthreads();
    }

    float4 bv4;
    bv4.x = bias[nn + tx*4 + 0];
    bv4.y = bias[nn + tx*4 + 1];
    bv4.z = bias[nn + tx*4 + 2];
    bv4.w = bias[nn + tx*4 + 3];
#pragma unroll
    for (int i = 0; i < 4; i++) {
        int m = bm + ty*4 + i;
        float4 r;
        r.x = acc[i][0] + bv4.x;
        r.y = acc[i][1] + bv4.y;
        r.z = acc[i][2] + bv4.z;
        r.w = acc[i][3] + bv4.w;
        *(float4*)(QKV + (size_t)m * NQKV + bn + tx*4) = r;
    }
}

// ---------------------------------------------------------------------------
// Kernel B: smem-tiled local attention.
// Block = 16x16 pixel tile of one (batch, head). Halo 22x22 of k (then v,
// buffer reused) in shared memory, padded to stride 20 floats per pixel
// (conflict-free LDS.128 across 8-lane phases).
// OOB halo pixels are ZERO-filled: score = qe exactly, v contribution = 0,
// matching the reference's pad-then-add-emb semantics with no divergence.
// ---------------------------------------------------------------------------
#define TILE    16
#define HALO    22              // TILE + 6
#define NHALO   (HALO*HALO)     // 484
#define PSTR    20              // padded floats per halo pixel

__global__ __launch_bounds__(256)
void attn_kernel(const float* __restrict__ QKV,
                 const float* __restrict__ emb0,   // [64,7]
                 const float* __restrict__ emb1,   // [64,7]
                 float* __restrict__ out)
{
    __shared__ float buf[NHALO * PSTR];            // 38,720 B

    const int tid = threadIdx.x;
    const int px  = tid & 15;          // pixel x within tile
    const int py  = tid >> 4;          // pixel y within tile
    const int tx0 = (blockIdx.x & 3) * TILE;
    const int ty0 = (blockIdx.x >> 2) * TILE;
    const int b   = blockIdx.y;
    const int h   = blockIdx.z;

    const int gx = tx0 + px;
    const int gy = ty0 + py;
    const int pix = ((b * HH) + gy) * WW + gx;

    // ---- load K halo (zero-filled OOB) ----
    {
        const int koff = FILTERS + h * HSIZE;
#pragma unroll
        for (int i = tid; i < NHALO * 4; i += 256) {
            const int hp = i >> 2, c4 = i & 3;
            const int hy = hp / HALO, hx = hp % HALO;
            const int sy = ty0 + hy - 3, sx = tx0 + hx - 3;
            float4 v = make_float4(0.f, 0.f, 0.f, 0.f);
            if ((unsigned)sy < HH && (unsigned)sx < WW) {
                const int sp = ((b * HH) + sy) * WW + sx;
                v = *(const float4*)(QKV + (size_t)sp * NQKV + koff + c4 * 4);
            }
            *(float4*)&buf[hp * PSTR + c4 * 4] = v;
        }
    }

    // ---- load q (global, own pixel) ----
    float q[16];
    {
        const float* qp = QKV + (size_t)pix * NQKV + h * HSIZE;
#pragma unroll
        for (int d = 0; d < 16; d += 4) {
            float4 v = *(const float4*)(qp + d);
            q[d+0] = v.x; q[d+1] = v.y; q[d+2] = v.z; q[d+3] = v.w;
        }
    }

    // ---- qe[r] = q . emb_row(h, :, r) ----
    float qe[7];
    {
        const bool use0 = (h < 4);
        const float* etab = use0 ? (emb0 + h * HSIZE * K0)
                                 : (emb1 + (h * HSIZE - 64) * K1);
#pragma unroll
        for (int r = 0; r < 7; r++) {
            float s = 0.f;
#pragma unroll
            for (int d = 0; d < 16; d++) s += q[d] * etab[d * 7 + r];
            qe[r] = s;
        }
        // replicate per-position base into a 49-agnostic accessor below via use0
        if (!use0) { /* qe indexed by dj */ }
    }
    const bool use0 = (h < 4);

    __syncthreads();

    // ---- scores from smem K ----
    float scores[KD];
    float mx = -1e30f;
#pragma unroll
    for (int p = 0; p < KD; p++) {
        const int di = p / 7, dj = p % 7;
        const int hp = (py + di) * HALO + (px + dj);
        const float* kp = &buf[hp * PSTR];
        float s = use0 ? qe[di] : qe[dj];
#pragma unroll
        for (int d = 0; d < 16; d += 4) {
            float4 kv = *(const float4*)(kp + d);
            s += q[d+0]*kv.x + q[d+1]*kv.y + q[d+2]*kv.z + q[d+3]*kv.w;
        }
        scores[p] = s;
        mx = fmaxf(mx, s);
    }

    // ---- softmax (weights, unnormalized) ----
    float sum = 0.f;
#pragma unroll
    for (int p = 0; p < KD; p++) {
        float e = __expf(scores[p] - mx);
        scores[p] = e;
        sum += e;
    }
    const float inv = 1.f / sum;

    // ---- reload buffer with V halo ----
    __syncthreads();
    {
        const int voff = 2 * FILTERS + h * HSIZE;
#pragma unroll
        for (int i = tid; i < NHALO * 4; i += 256) {
            const int hp = i >> 2, c4 = i & 3;
            const int hy = hp / HALO, hx = hp % HALO;
            const int sy = ty0 + hy - 3, sx = tx0 + hx - 3;
            float4 v = make_float4(0.f, 0.f, 0.f, 0.f);
            if ((unsigned)sy < HH && (unsigned)sx < WW) {
                const int sp = ((b * HH) + sy) * WW + sx;
                v = *(const float4*)(QKV + (size_t)sp * NQKV + voff + c4 * 4);
            }
            *(float4*)&buf[hp * PSTR + c4 * 4] = v;
        }
    }
    __syncthreads();

    // ---- weighted sum of V from smem ----
    float o[16];
#pragma unroll
    for (int d = 0; d < 16; d++) o[d] = 0.f;
#pragma unroll
    for (int p = 0; p < KD; p++) {
        const int di = p / 7, dj = p % 7;
        const int hp = (py + di) * HALO + (px + dj);
        const float* vp = &buf[hp * PSTR];
        const float w = scores[p];
#pragma unroll
        for (int d = 0; d < 16; d += 4) {
            float4 vv = *(const float4*)(vp + d);
            o[d+0] += w * vv.x; o[d+1] += w * vv.y;
            o[d+2] += w * vv.z; o[d+3] += w * vv.w;
        }
    }

    float* op = out + (size_t)pix * FILTERS + h * HSIZE;
#pragma unroll
    for (int d = 0; d < 16; d += 4) {
        float4 r;
        r.x = o[d+0]*inv; r.y = o[d+1]*inv; r.z = o[d+2]*inv; r.w = o[d+3]*inv;
        *(float4*)(op + d) = r;
    }
}

// ---------------------------------------------------------------------------
extern "C" void kernel_launch(void* const* d_in, const int* in_sizes, int n_in,
                              void* d_out, int out_size)
{
    const float* x    = (const float*)d_in[0];
    const float* Wq   = (const float*)d_in[1];
    const float* bq   = (const float*)d_in[2];
    const float* Wk   = (const float*)d_in[3];
    const float* bk   = (const float*)d_in[4];
    const float* Wv   = (const float*)d_in[5];
    const float* bv   = (const float*)d_in[6];
    const float* emb0 = (const float*)d_in[7];
    const float* emb1 = (const float*)d_in[8];
    float* out = (float*)d_out;

    float* qkv = nullptr;
    cudaGetSymbolAddress((void**)&qkv, g_QKV);

    dim3 gg(NPIX / BM, NQKV / BN);   // (256, 6)
    qkv_gemm_kernel<<<gg, 256>>>(x, Wq, bq, Wk, bk, Wv, bv, qkv);

    dim3 ga(16, BATCH, HEADS);       // 16 tiles, 4 batch, 8 heads = 512 blocks
    attn_kernel<<<ga, 256>>>(qkv, emb0, emb1, out);
}

// round 3
// speedup vs baseline: 2.2027x; 2.0233x over previous
#include <cuda_runtime.h>
#include <math.h>

// Problem constants
#define BATCH   4
#define HH      64
#define WW      64
#define CIN     128
#define FILTERS 128
#define HEADS   8
#define HSIZE   16
#define K0      7
#define K1      7
#define KD      49
#define NPIX    (BATCH*HH*WW)      // 16384
#define NQKV    384                 // q|k|v concat

__device__ float g_QKV[NPIX * NQKV];

// ---------------------------------------------------------------------------
// Kernel A: fused QKV projection.  C = X(16384x128) @ [Wq|Wk|Wv](128x384) + b
// BM=128, BN=64, BK=32, 256 threads, 8x4 microtile, double-buffered smem.
// ---------------------------------------------------------------------------
#define BM 128
#define BN 64
#define BK 32
#define XSTR (BM + 1)    // padded row stride to avoid transpose-store conflicts

__global__ __launch_bounds__(256)
void qkv_gemm_kernel(const float* __restrict__ X,
                     const float* __restrict__ Wq, const float* __restrict__ bq,
                     const float* __restrict__ Wk, const float* __restrict__ bk,
                     const float* __restrict__ Wv, const float* __restrict__ bv,
                     float* __restrict__ QKV)
{
    __shared__ float Xs[2][BK][XSTR];   // transposed X tiles
    __shared__ float Ws[2][BK][BN];

    const int bm = blockIdx.x * BM;
    const int bn = blockIdx.y * BN;

    const float* W;  const float* bias;  int nn;
    if (bn < 128)       { W = Wq; bias = bq; nn = bn; }
    else if (bn < 256)  { W = Wk; bias = bk; nn = bn - 128; }
    else                { W = Wv; bias = bv; nn = bn - 256; }

    const int tid = threadIdx.x;
    const int tx = tid & 15;
    const int ty = tid >> 4;

    float acc[8][4];
#pragma unroll
    for (int i = 0; i < 8; i++)
#pragma unroll
        for (int j = 0; j < 4; j++) acc[i][j] = 0.f;

    // ---- load first tiles directly into buffer 0 ----
#pragma unroll
    for (int l = 0; l < 4; l++) {               // X: 128 rows x 8 f4-cols
        const int idx = tid + l * 256;
        const int r = idx >> 3, c4 = idx & 7;
        float4 v = *(const float4*)(X + (size_t)(bm + r) * CIN + c4 * 4);
        Xs[0][c4*4+0][r] = v.x;
        Xs[0][c4*4+1][r] = v.y;
        Xs[0][c4*4+2][r] = v.z;
        Xs[0][c4*4+3][r] = v.w;
    }
#pragma unroll
    for (int l = 0; l < 2; l++) {               // W: 32 rows x 16 f4-cols
        const int idx = tid + l * 256;
        const int r = idx >> 4, c4 = idx & 15;
        *(float4*)&Ws[0][r][c4*4] =
            *(const float4*)(W + (size_t)r * FILTERS + nn + c4*4);
    }
    __syncthreads();

    int cur = 0;
#pragma unroll
    for (int kt = 0; kt < CIN / BK; kt++) {
        const int k_next = (kt + 1) * BK;
        float4 pa[4], pw[2];
        if (k_next < CIN) {
#pragma unroll
            for (int l = 0; l < 4; l++) {
                const int idx = tid + l * 256;
                const int r = idx >> 3, c4 = idx & 7;
                pa[l] = *(const float4*)(X + (size_t)(bm + r) * CIN + k_next + c4*4);
            }
#pragma unroll
            for (int l = 0; l < 2; l++) {
                const int idx = tid + l * 256;
                const int r = idx >> 4, c4 = idx & 15;
                pw[l] = *(const float4*)(W + (size_t)(k_next + r) * FILTERS + nn + c4*4);
            }
        }

#pragma unroll
        for (int kk = 0; kk < BK; kk++) {
            float a[8], b[4];
#pragma unroll
            for (int i = 0; i < 4; i++) {
                a[i]     = Xs[cur][kk][ty*4 + i];
                a[4 + i] = Xs[cur][kk][64 + ty*4 + i];
            }
#pragma unroll
            for (int j = 0; j < 4; j++) b[j] = Ws[cur][kk][tx*4 + j];
#pragma unroll
            for (int i = 0; i < 8; i++)
#pragma unroll
                for (int j = 0; j < 4; j++) acc[i][j] += a[i] * b[j];
        }

        if (k_next < CIN) {
            const int nxt = cur ^ 1;
#pragma unroll
            for (int l = 0; l < 4; l++) {
                const int idx = tid + l * 256;
                const int r = idx >> 3, c4 = idx & 7;
                Xs[nxt][c4*4+0][r] = pa[l].x;
                Xs[nxt][c4*4+1][r] = pa[l].y;
                Xs[nxt][c4*4+2][r] = pa[l].z;
                Xs[nxt][c4*4+3][r] = pa[l].w;
            }
#pragma unroll
            for (int l = 0; l < 2; l++) {
                const int idx = tid + l * 256;
                const int r = idx >> 4, c4 = idx & 15;
                *(float4*)&Ws[nxt][r][c4*4] = pw[l];
            }
            __syncthreads();
            cur = nxt;
        }
    }

    // epilogue
    float4 bv4;
    bv4.x = bias[nn + tx*4 + 0];
    bv4.y = bias[nn + tx*4 + 1];
    bv4.z = bias[nn + tx*4 + 2];
    bv4.w = bias[nn + tx*4 + 3];
#pragma unroll
    for (int g = 0; g < 2; g++) {
#pragma unroll
        for (int i = 0; i < 4; i++) {
            const int m = bm + g * 64 + ty*4 + i;
            float4 r;
            r.x = acc[g*4 + i][0] + bv4.x;
            r.y = acc[g*4 + i][1] + bv4.y;
            r.z = acc[g*4 + i][2] + bv4.z;
            r.w = acc[g*4 + i][3] + bv4.w;
            *(float4*)(QKV + (size_t)m * NQKV + bn + tx*4) = r;
        }
    }
}

// ---------------------------------------------------------------------------
// Kernel B: smem-tiled local attention.
// Block = 16(w) x 8(h) pixel tile of one (batch, head), 128 threads.
// Halo 14x22 of k (then v, buffer reused) in smem, PSTR=20 conflict-free.
// OOB halo zero-filled: score = qe exactly, v contribution = 0.
// ---------------------------------------------------------------------------
#define TW      16
#define TH      8
#define HW      22              // TW + 6
#define HHALO   14              // TH + 6
#define NHALO   (HW*HHALO)      // 308
#define PSTR    20

__global__ __launch_bounds__(128)
void attn_kernel(const float* __restrict__ QKV,
                 const float* __restrict__ emb0,   // [64,7]
                 const float* __restrict__ emb1,   // [64,7]
                 float* __restrict__ out)
{
    __shared__ float buf[NHALO * PSTR];            // 24,640 B

    const int tid = threadIdx.x;
    const int px  = tid & 15;
    const int py  = tid >> 4;          // 0..7
    const int tx0 = (blockIdx.x & 3) * TW;
    const int ty0 = (blockIdx.x >> 2) * TH;
    const int b   = blockIdx.y;
    const int h   = blockIdx.z;

    const int gx = tx0 + px;
    const int gy = ty0 + py;
    const int pix = ((b * HH) + gy) * WW + gx;

    // ---- load K halo (zero-filled OOB) ----
    {
        const int koff = FILTERS + h * HSIZE;
#pragma unroll
        for (int i = tid; i < NHALO * 4; i += 128) {
            const int hp = i >> 2, c4 = i & 3;
            const int hy = hp / HW, hx = hp % HW;
            const int sy = ty0 + hy - 3, sx = tx0 + hx - 3;
            float4 v = make_float4(0.f, 0.f, 0.f, 0.f);
            if ((unsigned)sy < HH && (unsigned)sx < WW) {
                const int sp = ((b * HH) + sy) * WW + sx;
                v = *(const float4*)(QKV + (size_t)sp * NQKV + koff + c4 * 4);
            }
            *(float4*)&buf[hp * PSTR + c4 * 4] = v;
        }
    }

    // ---- load q ----
    float q[16];
    {
        const float* qp = QKV + (size_t)pix * NQKV + h * HSIZE;
#pragma unroll
        for (int d = 0; d < 16; d += 4) {
            float4 v = *(const float4*)(qp + d);
            q[d+0] = v.x; q[d+1] = v.y; q[d+2] = v.z; q[d+3] = v.w;
        }
    }

    // ---- qe[r] = q . emb_row(h, :, r) ----
    const bool use0 = (h < 4);
    float qe[7];
    {
        const float* etab = use0 ? (emb0 + h * HSIZE * K0)
                                 : (emb1 + (h * HSIZE - 64) * K1);
#pragma unroll
        for (int r = 0; r < 7; r++) {
            float s = 0.f;
#pragma unroll
            for (int d = 0; d < 16; d++) s += q[d] * etab[d * 7 + r];
            qe[r] = s;
        }
    }

    __syncthreads();

    // ---- scores from smem K ----
    float scores[KD];
    float mx = -1e30f;
#pragma unroll
    for (int p = 0; p < KD; p++) {
        const int di = p / 7, dj = p % 7;
        const float* kp = &buf[((py + di) * HW + (px + dj)) * PSTR];
        float s = use0 ? qe[di] : qe[dj];
#pragma unroll
        for (int d = 0; d < 16; d += 4) {
            float4 kv = *(const float4*)(kp + d);
            s += q[d+0]*kv.x + q[d+1]*kv.y + q[d+2]*kv.z + q[d+3]*kv.w;
        }
        scores[p] = s;
        mx = fmaxf(mx, s);
    }

    // ---- softmax weights ----
    float sum = 0.f;
#pragma unroll
    for (int p = 0; p < KD; p++) {
        float e = __expf(scores[p] - mx);
        scores[p] = e;
        sum += e;
    }
    const float inv = 1.f / sum;

    // ---- reload buffer with V halo ----
    __syncthreads();
    {
        const int voff = 2 * FILTERS + h * HSIZE;
#pragma unroll
        for (int i = tid; i < NHALO * 4; i += 128) {
            const int hp = i >> 2, c4 = i & 3;
            const int hy = hp / HW, hx = hp % HW;
            const int sy = ty0 + hy - 3, sx = tx0 + hx - 3;
            float4 v = make_float4(0.f, 0.f, 0.f, 0.f);
            if ((unsigned)sy < HH && (unsigned)sx < WW) {
                const int sp = ((b * HH) + sy) * WW + sx;
                v = *(const float4*)(QKV + (size_t)sp * NQKV + voff + c4 * 4);
            }
            *(float4*)&buf[hp * PSTR + c4 * 4] = v;
        }
    }
    __syncthreads();

    // ---- weighted sum of V from smem ----
    float o[16];
#pragma unroll
    for (int d = 0; d < 16; d++) o[d] = 0.f;
#pragma unroll
    for (int p = 0; p < KD; p++) {
        const int di = p / 7, dj = p % 7;
        const float* vp = &buf[((py + di) * HW + (px + dj)) * PSTR];
        const float w = scores[p];
#pragma unroll
        for (int d = 0; d < 16; d += 4) {
            float4 vv = *(const float4*)(vp + d);
            o[d+0] += w * vv.x; o[d+1] += w * vv.y;
            o[d+2] += w * vv.z; o[d+3] += w * vv.w;
        }
    }

    float* op = out + (size_t)pix * FILTERS + h * HSIZE;
#pragma unroll
    for (int d = 0; d < 16; d += 4) {
        float4 r;
        r.x = o[d+0]*inv; r.y = o[d+1]*inv; r.z = o[d+2]*inv; r.w = o[d+3]*inv;
        *(float4*)(op + d) = r;
    }
}

// ---------------------------------------------------------------------------
extern "C" void kernel_launch(void* const* d_in, const int* in_sizes, int n_in,
                              void* d_out, int out_size)
{
    const float* x    = (const float*)d_in[0];
    const float* Wq   = (const float*)d_in[1];
    const float* bq   = (const float*)d_in[2];
    const float* Wk   = (const float*)d_in[3];
    const float* bk   = (const float*)d_in[4];
    const float* Wv   = (const float*)d_in[5];
    const float* bv   = (const float*)d_in[6];
    const float* emb0 = (const float*)d_in[7];
    const float* emb1 = (const float*)d_in[8];
    float* out = (float*)d_out;

    float* qkv = nullptr;
    cudaGetSymbolAddress((void**)&qkv, g_QKV);

    dim3 gg(NPIX / BM, NQKV / BN);   // (128, 6)
    qkv_gemm_kernel<<<gg, 256>>>(x, Wq, bq, Wk, bk, Wv, bv, qkv);

    dim3 ga(32, BATCH, HEADS);       // 32 tiles, 4 batch, 8 heads = 1024 blocks
    attn_kernel<<<ga, 128>>>(qkv, emb0, emb1, out);
}

// round 4
// speedup vs baseline: 2.3902x; 1.0851x over previous
#include <cuda_runtime.h>
#include <math.h>

// Problem constants
#define BATCH   4
#define HH      64
#define WW      64
#define CIN     128
#define FILTERS 128
#define HEADS   8
#define HSIZE   16
#define K0      7
#define K1      7
#define KD      49
#define NPIX    (BATCH*HH*WW)      // 16384
#define NQKV    384                 // q|k|v concat

typedef unsigned long long ull;

// packed f32x2 helpers (sm_100+)
#define FMA2(d, a, b)   asm("fma.rn.f32x2 %0, %1, %2, %0;" : "+l"(d) : "l"(a), "l"(b))
#define MUL2(d, a, b)   asm("mul.rn.f32x2 %0, %1, %2;"     : "=l"(d) : "l"(a), "l"(b))
#define PACK2(d, x, y)  asm("mov.b64 %0, {%1, %2};" : "=l"(d) : "f"(x), "f"(y))
#define UNPK2(lo, hi, s) asm("mov.b64 {%0, %1}, %2;" : "=f"(lo), "=f"(hi) : "l"(s))

__device__ float g_QKV[NPIX * NQKV];

// ---------------------------------------------------------------------------
// Kernel A: fused QKV projection with packed f32x2 FMA.
// C = X(16384x128) @ [Wq|Wk|Wv](128x384) + b
// BM=128, BN=64, BK=32, 256 threads, 8x4 microtile, double-buffered smem.
// ---------------------------------------------------------------------------
#define BM 128
#define BN 64
#define BK 32
#define XSTR (BM + 1)

__global__ __launch_bounds__(256)
void qkv_gemm_kernel(const float* __restrict__ X,
                     const float* __restrict__ Wq, const float* __restrict__ bq,
                     const float* __restrict__ Wk, const float* __restrict__ bk,
                     const float* __restrict__ Wv, const float* __restrict__ bv,
                     float* __restrict__ QKV)
{
    __shared__ float Xs[2][BK][XSTR];
    __shared__ float Ws[2][BK][BN];

    const int bm = blockIdx.x * BM;
    const int bn = blockIdx.y * BN;

    const float* W;  const float* bias;  int nn;
    if (bn < 128)       { W = Wq; bias = bq; nn = bn; }
    else if (bn < 256)  { W = Wk; bias = bk; nn = bn - 128; }
    else                { W = Wv; bias = bv; nn = bn - 256; }

    const int tid = threadIdx.x;
    const int tx = tid & 15;
    const int ty = tid >> 4;

    ull acc01[8], acc23[8];
#pragma unroll
    for (int i = 0; i < 8; i++) { acc01[i] = 0ull; acc23[i] = 0ull; }

    // first tiles into buffer 0
#pragma unroll
    for (int l = 0; l < 4; l++) {
        const int idx = tid + l * 256;
        const int r = idx >> 3, c4 = idx & 7;
        float4 v = *(const float4*)(X + (size_t)(bm + r) * CIN + c4 * 4);
        Xs[0][c4*4+0][r] = v.x;
        Xs[0][c4*4+1][r] = v.y;
        Xs[0][c4*4+2][r] = v.z;
        Xs[0][c4*4+3][r] = v.w;
    }
#pragma unroll
    for (int l = 0; l < 2; l++) {
        const int idx = tid + l * 256;
        const int r = idx >> 4, c4 = idx & 15;
        *(float4*)&Ws[0][r][c4*4] =
            *(const float4*)(W + (size_t)r * FILTERS + nn + c4*4);
    }
    __syncthreads();

    int cur = 0;
#pragma unroll
    for (int kt = 0; kt < CIN / BK; kt++) {
        const int k_next = (kt + 1) * BK;
        float4 pa[4], pw[2];
        if (k_next < CIN) {
#pragma unroll
            for (int l = 0; l < 4; l++) {
                const int idx = tid + l * 256;
                const int r = idx >> 3, c4 = idx & 7;
                pa[l] = *(const float4*)(X + (size_t)(bm + r) * CIN + k_next + c4*4);
            }
#pragma unroll
            for (int l = 0; l < 2; l++) {
                const int idx = tid + l * 256;
                const int r = idx >> 4, c4 = idx & 15;
                pw[l] = *(const float4*)(W + (size_t)(k_next + r) * FILTERS + nn + c4*4);
            }
        }

#pragma unroll
        for (int kk = 0; kk < BK; kk++) {
            // b pair: 4 consecutive floats = 2 f32x2
            ulonglong2 bb = *(const ulonglong2*)&Ws[cur][kk][tx*4];
            float a[8];
#pragma unroll
            for (int i = 0; i < 4; i++) {
                a[i]     = Xs[cur][kk][ty*4 + i];
                a[4 + i] = Xs[cur][kk][64 + ty*4 + i];
            }
#pragma unroll
            for (int i = 0; i < 8; i++) {
                ull ap;
                PACK2(ap, a[i], a[i]);
                FMA2(acc01[i], ap, bb.x);
                FMA2(acc23[i], ap, bb.y);
            }
        }

        if (k_next < CIN) {
            const int nxt = cur ^ 1;
#pragma unroll
            for (int l = 0; l < 4; l++) {
                const int idx = tid + l * 256;
                const int r = idx >> 3, c4 = idx & 7;
                Xs[nxt][c4*4+0][r] = pa[l].x;
                Xs[nxt][c4*4+1][r] = pa[l].y;
                Xs[nxt][c4*4+2][r] = pa[l].z;
                Xs[nxt][c4*4+3][r] = pa[l].w;
            }
#pragma unroll
            for (int l = 0; l < 2; l++) {
                const int idx = tid + l * 256;
                const int r = idx >> 4, c4 = idx & 15;
                *(float4*)&Ws[nxt][r][c4*4] = pw[l];
            }
            __syncthreads();
            cur = nxt;
        }
    }

    // epilogue
    float4 bv4;
    bv4.x = bias[nn + tx*4 + 0];
    bv4.y = bias[nn + tx*4 + 1];
    bv4.z = bias[nn + tx*4 + 2];
    bv4.w = bias[nn + tx*4 + 3];
#pragma unroll
    for (int g = 0; g < 2; g++) {
#pragma unroll
        for (int i = 0; i < 4; i++) {
            const int m = bm + g * 64 + ty*4 + i;
            float c0, c1, c2, c3;
            UNPK2(c0, c1, acc01[g*4 + i]);
            UNPK2(c2, c3, acc23[g*4 + i]);
            float4 r;
            r.x = c0 + bv4.x;
            r.y = c1 + bv4.y;
            r.z = c2 + bv4.z;
            r.w = c3 + bv4.w;
            *(float4*)(QKV + (size_t)m * NQKV + bn + tx*4) = r;
        }
    }
}

// ---------------------------------------------------------------------------
// Kernel B: pixel-pair one-pass local attention.
// Block = 16x16 tile, 128 threads; thread t = (px, yp) owns pixels
// (px, 2*yp) and (px, 2*yp+1). Union window: 8 rows x 7 cols = 56 positions
// serving both pixels (43% less LDS traffic than per-pixel).
// K and V halos (22x22, stride 20, conflict-free) both resident: 77.4 KB
// dynamic smem. One pass, no-max softmax (|score| <~ 30 << 88, exact math
// is shift-invariant). OOB halo zero-filled (score = qe term only, v = 0).
// ---------------------------------------------------------------------------
#define TILE    16
#define HALO    22
#define NHALO   (HALO*HALO)     // 484
#define PSTR    20
#define ATTN_SMEM (2 * NHALO * PSTR * 4)   // 77440 B

__global__ __launch_bounds__(128)
void attn_kernel(const float* __restrict__ QKV,
                 const float* __restrict__ emb0,   // [64,7]
                 const float* __restrict__ emb1,   // [64,7]
                 float* __restrict__ out)
{
    extern __shared__ float sbuf[];
    float* bufK = sbuf;
    float* bufV = sbuf + NHALO * PSTR;

    const int tid = threadIdx.x;
    const int px  = tid & 15;
    const int yp  = tid >> 4;          // 0..7
    const int tx0 = (blockIdx.x & 3) * TILE;
    const int ty0 = (blockIdx.x >> 2) * TILE;
    const int b   = blockIdx.y;
    const int h   = blockIdx.z;

    // ---- load K and V halos (zero-filled OOB) ----
    {
        const int koff = FILTERS + h * HSIZE;
        const int voff = 2 * FILTERS + h * HSIZE;
#pragma unroll
        for (int i = tid; i < NHALO * 4; i += 128) {
            const int hp = i >> 2, c4 = i & 3;
            const int hy = hp / HALO, hx = hp % HALO;
            const int sy = ty0 + hy - 3, sx = tx0 + hx - 3;
            float4 kv = make_float4(0.f, 0.f, 0.f, 0.f);
            float4 vv = make_float4(0.f, 0.f, 0.f, 0.f);
            if ((unsigned)sy < HH && (unsigned)sx < WW) {
                const float* base = QKV + (size_t)(((b * HH) + sy) * WW + sx) * NQKV;
                kv = *(const float4*)(base + koff + c4 * 4);
                vv = *(const float4*)(base + voff + c4 * 4);
            }
            *(float4*)&bufK[hp * PSTR + c4 * 4] = kv;
            *(float4*)&bufV[hp * PSTR + c4 * 4] = vv;
        }
    }

    // ---- load both q vectors as packed pairs ----
    const int y0   = ty0 + 2 * yp;
    const int pix0 = ((b * HH) + y0) * WW + (tx0 + px);
    const int pix1 = pix0 + WW;

    ull q0[8], q1[8];
    {
        const ulonglong2* qp0 = (const ulonglong2*)(QKV + (size_t)pix0 * NQKV + h * HSIZE);
        const ulonglong2* qp1 = (const ulonglong2*)(QKV + (size_t)pix1 * NQKV + h * HSIZE);
#pragma unroll
        for (int j = 0; j < 4; j++) {
            ulonglong2 t0 = qp0[j];
            ulonglong2 t1 = qp1[j];
            q0[2*j] = t0.x; q0[2*j+1] = t0.y;
            q1[2*j] = t1.x; q1[2*j+1] = t1.y;
        }
    }

    // ---- qe tables for both pixels ----
    const bool use0 = (h < 4);
    float qe0[7], qe1[7];
    {
        const float* etab = use0 ? (emb0 + h * HSIZE * K0)
                                 : (emb1 + (h * HSIZE - 64) * K1);
        float qf0[16], qf1[16];
#pragma unroll
        for (int j = 0; j < 8; j++) {
            UNPK2(qf0[2*j], qf0[2*j+1], q0[j]);
            UNPK2(qf1[2*j], qf1[2*j+1], q1[j]);
        }
#pragma unroll
        for (int r = 0; r < 7; r++) {
            float s0 = 0.f, s1 = 0.f;
#pragma unroll
            for (int d = 0; d < 16; d++) {
                const float e = etab[d * 7 + r];
                s0 += qf0[d] * e;
                s1 += qf1[d] * e;
            }
            qe0[r] = s0;
            qe1[r] = s1;
        }
    }

    __syncthreads();

    // ---- one-pass online (no-max) softmax-attention over union window ----
    float sum0 = 0.f, sum1 = 0.f;
    ull o0[8], o1[8];
#pragma unroll
    for (int j = 0; j < 8; j++) { o0[j] = 0ull; o1[j] = 0ull; }

#pragma unroll
    for (int dr = 0; dr < 8; dr++) {
#pragma unroll
        for (int dj = 0; dj < 7; dj++) {
            const int eoff = ((2*yp + dr) * HALO + (px + dj)) * PSTR;
            const float* kp = bufK + eoff;
            const float* vp = bufV + eoff;
            ull kr[8], vr[8];
            {
                ulonglong2 t;
                t = *(const ulonglong2*)(kp +  0); kr[0]=t.x; kr[1]=t.y;
                t = *(const ulonglong2*)(kp +  4); kr[2]=t.x; kr[3]=t.y;
                t = *(const ulonglong2*)(kp +  8); kr[4]=t.x; kr[5]=t.y;
                t = *(const ulonglong2*)(kp + 12); kr[6]=t.x; kr[7]=t.y;
                t = *(const ulonglong2*)(vp +  0); vr[0]=t.x; vr[1]=t.y;
                t = *(const ulonglong2*)(vp +  4); vr[2]=t.x; vr[3]=t.y;
                t = *(const ulonglong2*)(vp +  8); vr[4]=t.x; vr[5]=t.y;
                t = *(const ulonglong2*)(vp + 12); vr[6]=t.x; vr[7]=t.y;
            }

            if (dr < 7) {           // pixel0: di = dr
                ull acc;
                MUL2(acc, q0[0], kr[0]);
#pragma unroll
                for (int j = 1; j < 8; j++) FMA2(acc, q0[j], kr[j]);
                float lo, hi;
                UNPK2(lo, hi, acc);
                const float s = lo + hi + (use0 ? qe0[dr] : qe0[dj]);
                const float e = __expf(s);
                sum0 += e;
                ull ep; PACK2(ep, e, e);
#pragma unroll
                for (int j = 0; j < 8; j++) FMA2(o0[j], ep, vr[j]);
            }
            if (dr > 0) {           // pixel1: di = dr-1
                ull acc;
                MUL2(acc, q1[0], kr[0]);
#pragma unroll
                for (int j = 1; j < 8; j++) FMA2(acc, q1[j], kr[j]);
                float lo, hi;
                UNPK2(lo, hi, acc);
                const float s = lo + hi + (use0 ? qe1[dr-1] : qe1[dj]);
                const float e = __expf(s);
                sum1 += e;
                ull ep; PACK2(ep, e, e);
#pragma unroll
                for (int j = 0; j < 8; j++) FMA2(o1[j], ep, vr[j]);
            }
        }
    }

    // ---- normalize + store both pixels ----
    const float inv0 = 1.f / sum0;
    const float inv1 = 1.f / sum1;
    float* op0 = out + (size_t)pix0 * FILTERS + h * HSIZE;
    float* op1 = out + (size_t)pix1 * FILTERS + h * HSIZE;
#pragma unroll
    for (int j = 0; j < 4; j++) {
        float a0, a1, b0, b1;
        UNPK2(a0, a1, o0[2*j]);
        UNPK2(b0, b1, o0[2*j+1]);
        float4 r0 = make_float4(a0*inv0, a1*inv0, b0*inv0, b1*inv0);
        *(float4*)(op0 + j*4) = r0;
        UNPK2(a0, a1, o1[2*j]);
        UNPK2(b0, b1, o1[2*j+1]);
        float4 r1 = make_float4(a0*inv1, a1*inv1, b0*inv1, b1*inv1);
        *(float4*)(op1 + j*4) = r1;
    }
}

// ---------------------------------------------------------------------------
extern "C" void kernel_launch(void* const* d_in, const int* in_sizes, int n_in,
                              void* d_out, int out_size)
{
    const float* x    = (const float*)d_in[0];
    const float* Wq   = (const float*)d_in[1];
    const float* bq   = (const float*)d_in[2];
    const float* Wk   = (const float*)d_in[3];
    const float* bk   = (const float*)d_in[4];
    const float* Wv   = (const float*)d_in[5];
    const float* bv   = (const float*)d_in[6];
    const float* emb0 = (const float*)d_in[7];
    const float* emb1 = (const float*)d_in[8];
    float* out = (float*)d_out;

    float* qkv = nullptr;
    cudaGetSymbolAddress((void**)&qkv, g_QKV);

    cudaFuncSetAttribute(attn_kernel,
                         cudaFuncAttributeMaxDynamicSharedMemorySize, ATTN_SMEM);

    dim3 gg(NPIX / BM, NQKV / BN);   // (128, 6)
    qkv_gemm_kernel<<<gg, 256>>>(x, Wq, bq, Wk, bk, Wv, bv, qkv);

    dim3 ga(16, BATCH, HEADS);       // 16 tiles, 4 batch, 8 heads = 512 blocks
    attn_kernel<<<ga, 128, ATTN_SMEM>>>(qkv, emb0, emb1, out);
}

// round 5
// speedup vs baseline: 2.5473x; 1.0657x over previous
#include <cuda_runtime.h>
#include <mma.h>
#include <math.h>

using namespace nvcuda;

// Problem constants
#define BATCH   4
#define HH      64
#define WW      64
#define CIN     128
#define FILTERS 128
#define HEADS   8
#define HSIZE   16
#define K0      7
#define K1      7
#define KD      49
#define NPIX    (BATCH*HH*WW)      // 16384
#define NQKV    384                 // q|k|v concat

typedef unsigned long long ull;

// packed f32x2 helpers (sm_100+)
#define FMA2(d, a, b)   asm("fma.rn.f32x2 %0, %1, %2, %0;" : "+l"(d) : "l"(a), "l"(b))
#define MUL2(d, a, b)   asm("mul.rn.f32x2 %0, %1, %2;"     : "=l"(d) : "l"(a), "l"(b))
#define ADD2(d, a, b)   asm("add.rn.f32x2 %0, %1, %2;"     : "=l"(d) : "l"(a), "l"(b))
#define PACK2(d, x, y)  asm("mov.b64 %0, {%1, %2};" : "=l"(d) : "f"(x), "f"(y))
#define UNPK2(lo, hi, s) asm("mov.b64 {%0, %1}, %2;" : "=f"(lo), "=f"(hi) : "l"(s))

__device__ float g_QKV[NPIX * NQKV];

// ---------------------------------------------------------------------------
// Kernel A: fused QKV projection on tensor cores (TF32 WMMA m16n16k8).
// C = X(16384x128) @ [Wq|Wk|Wv](128x384) + b
// Block: BM=128 x BN=64, 256 threads (8 warps, 4x2), each warp 32x32 (2x2 frags).
// ---------------------------------------------------------------------------
#define GBM 128
#define GBN 64
#define GBK 32
#define ALD 36      // As row stride (floats)
#define BLD 68      // Ws row stride
#define CLD 68      // staging row stride

__global__ __launch_bounds__(256)
void qkv_gemm_kernel(const float* __restrict__ X,
                     const float* __restrict__ Wq, const float* __restrict__ bq,
                     const float* __restrict__ Wk, const float* __restrict__ bk,
                     const float* __restrict__ Wv, const float* __restrict__ bv,
                     float* __restrict__ QKV)
{
    __shared__ union {
        struct {
            float A[GBM][ALD];      // X tile: 128 x 32 (row-major, padded)
            float B[GBK][BLD];      // W tile: 32 x 64
        } in;
        float C[GBM][CLD];          // output staging
    } sm;

    const int bm = blockIdx.x * GBM;
    const int bn = blockIdx.y * GBN;

    const float* W;  const float* bias;  int nn;
    if (bn < 128)       { W = Wq; bias = bq; nn = bn; }
    else if (bn < 256)  { W = Wk; bias = bk; nn = bn - 128; }
    else                { W = Wv; bias = bv; nn = bn - 256; }

    const int tid = threadIdx.x;
    const int wid = tid >> 5;
    const int warp_m = wid & 3;       // 4 row-warps of 32 rows
    const int warp_n = wid >> 2;      // 2 col-warps of 32 cols

    wmma::fragment<wmma::accumulator, 16, 16, 8, float> acc[2][2];
#pragma unroll
    for (int i = 0; i < 2; i++)
#pragma unroll
        for (int j = 0; j < 2; j++) wmma::fill_fragment(acc[i][j], 0.f);

    for (int kt = 0; kt < CIN; kt += GBK) {
        // load X tile: 128 rows x 8 float4
#pragma unroll
        for (int l = 0; l < 4; l++) {
            const int idx = tid + l * 256;
            const int r = idx >> 3, c4 = idx & 7;
            float4 v = *(const float4*)(X + (size_t)(bm + r) * CIN + kt + c4 * 4);
            *(float4*)&sm.in.A[r][c4 * 4] = v;
        }
        // load W tile: 32 rows x 16 float4
#pragma unroll
        for (int l = 0; l < 2; l++) {
            const int idx = tid + l * 256;
            const int r = idx >> 4, c4 = idx & 15;
            *(float4*)&sm.in.B[r][c4 * 4] =
                *(const float4*)(W + (size_t)(kt + r) * FILTERS + nn + c4 * 4);
        }
        __syncthreads();

#pragma unroll
        for (int ks = 0; ks < GBK; ks += 8) {
            wmma::fragment<wmma::matrix_a, 16, 16, 8, wmma::precision::tf32, wmma::row_major> af[2];
            wmma::fragment<wmma::matrix_b, 16, 16, 8, wmma::precision::tf32, wmma::row_major> bf[2];
#pragma unroll
            for (int i = 0; i < 2; i++) {
                wmma::load_matrix_sync(af[i], &sm.in.A[warp_m * 32 + i * 16][ks], ALD);
#pragma unroll
                for (int e = 0; e < af[i].num_elements; e++)
                    af[i].x[e] = wmma::__float_to_tf32(af[i].x[e]);
            }
#pragma unroll
            for (int j = 0; j < 2; j++) {
                wmma::load_matrix_sync(bf[j], &sm.in.B[ks][warp_n * 32 + j * 16], BLD);
#pragma unroll
                for (int e = 0; e < bf[j].num_elements; e++)
                    bf[j].x[e] = wmma::__float_to_tf32(bf[j].x[e]);
            }
#pragma unroll
            for (int i = 0; i < 2; i++)
#pragma unroll
                for (int j = 0; j < 2; j++)
                    wmma::mma_sync(acc[i][j], af[i], bf[j], acc[i][j]);
        }
        __syncthreads();
    }

    // stage to smem, add bias, write out
#pragma unroll
    for (int i = 0; i < 2; i++)
#pragma unroll
        for (int j = 0; j < 2; j++)
            wmma::store_matrix_sync(&sm.C[warp_m * 32 + i * 16][warp_n * 32 + j * 16],
                                    acc[i][j], CLD, wmma::mem_row_major);
    __syncthreads();

#pragma unroll
    for (int l = 0; l < 8; l++) {              // 128 rows x 16 f4 = 2048 / 256
        const int idx = tid + l * 256;
        const int r = idx >> 4, c4 = idx & 15;
        float4 v = *(float4*)&sm.C[r][c4 * 4];
        v.x += bias[nn + c4 * 4 + 0];
        v.y += bias[nn + c4 * 4 + 1];
        v.z += bias[nn + c4 * 4 + 2];
        v.w += bias[nn + c4 * 4 + 3];
        *(float4*)(QKV + (size_t)(bm + r) * NQKV + bn + c4 * 4) = v;
    }
}

// ---------------------------------------------------------------------------
// Kernel B: pixel-pair one-pass local attention (unchanged structure from R4,
// dot product split into two chains + ADD2 to cut serial latency).
// ---------------------------------------------------------------------------
#define TILE    16
#define HALO    22
#define NHALO   (HALO*HALO)     // 484
#define PSTR    20
#define ATTN_SMEM (2 * NHALO * PSTR * 4)   // 77440 B

__global__ __launch_bounds__(128)
void attn_kernel(const float* __restrict__ QKV,
                 const float* __restrict__ emb0,   // [64,7]
                 const float* __restrict__ emb1,   // [64,7]
                 float* __restrict__ out)
{
    extern __shared__ float sbuf[];
    float* bufK = sbuf;
    float* bufV = sbuf + NHALO * PSTR;

    const int tid = threadIdx.x;
    const int px  = tid & 15;
    const int yp  = tid >> 4;          // 0..7
    const int tx0 = (blockIdx.x & 3) * TILE;
    const int ty0 = (blockIdx.x >> 2) * TILE;
    const int b   = blockIdx.y;
    const int h   = blockIdx.z;

    // ---- load K and V halos (zero-filled OOB) ----
    {
        const int koff = FILTERS + h * HSIZE;
        const int voff = 2 * FILTERS + h * HSIZE;
#pragma unroll
        for (int i = tid; i < NHALO * 4; i += 128) {
            const int hp = i >> 2, c4 = i & 3;
            const int hy = hp / HALO, hx = hp % HALO;
            const int sy = ty0 + hy - 3, sx = tx0 + hx - 3;
            float4 kv = make_float4(0.f, 0.f, 0.f, 0.f);
            float4 vv = make_float4(0.f, 0.f, 0.f, 0.f);
            if ((unsigned)sy < HH && (unsigned)sx < WW) {
                const float* base = QKV + (size_t)(((b * HH) + sy) * WW + sx) * NQKV;
                kv = *(const float4*)(base + koff + c4 * 4);
                vv = *(const float4*)(base + voff + c4 * 4);
            }
            *(float4*)&bufK[hp * PSTR + c4 * 4] = kv;
            *(float4*)&bufV[hp * PSTR + c4 * 4] = vv;
        }
    }

    // ---- load both q vectors as packed pairs ----
    const int y0   = ty0 + 2 * yp;
    const int pix0 = ((b * HH) + y0) * WW + (tx0 + px);
    const int pix1 = pix0 + WW;

    ull q0[8], q1[8];
    {
        const ulonglong2* qp0 = (const ulonglong2*)(QKV + (size_t)pix0 * NQKV + h * HSIZE);
        const ulonglong2* qp1 = (const ulonglong2*)(QKV + (size_t)pix1 * NQKV + h * HSIZE);
#pragma unroll
        for (int j = 0; j < 4; j++) {
            ulonglong2 t0 = qp0[j];
            ulonglong2 t1 = qp1[j];
            q0[2*j] = t0.x; q0[2*j+1] = t0.y;
            q1[2*j] = t1.x; q1[2*j+1] = t1.y;
        }
    }

    // ---- qe tables for both pixels ----
    const bool use0 = (h < 4);
    float qe0[7], qe1[7];
    {
        const float* etab = use0 ? (emb0 + h * HSIZE * K0)
                                 : (emb1 + (h * HSIZE - 64) * K1);
        float qf0[16], qf1[16];
#pragma unroll
        for (int j = 0; j < 8; j++) {
            UNPK2(qf0[2*j], qf0[2*j+1], q0[j]);
            UNPK2(qf1[2*j], qf1[2*j+1], q1[j]);
        }
#pragma unroll
        for (int r = 0; r < 7; r++) {
            float s0 = 0.f, s1 = 0.f;
#pragma unroll
            for (int d = 0; d < 16; d++) {
                const float e = etab[d * 7 + r];
                s0 += qf0[d] * e;
                s1 += qf1[d] * e;
            }
            qe0[r] = s0;
            qe1[r] = s1;
        }
    }

    __syncthreads();

    // ---- one-pass (no-max) softmax-attention over union window ----
    float sum0 = 0.f, sum1 = 0.f;
    ull o0[8], o1[8];
#pragma unroll
    for (int j = 0; j < 8; j++) { o0[j] = 0ull; o1[j] = 0ull; }

#pragma unroll
    for (int dr = 0; dr < 8; dr++) {
#pragma unroll
        for (int dj = 0; dj < 7; dj++) {
            const int eoff = ((2*yp + dr) * HALO + (px + dj)) * PSTR;
            const float* kp = bufK + eoff;
            const float* vp = bufV + eoff;
            ull kr[8], vr[8];
            {
                ulonglong2 t;
                t = *(const ulonglong2*)(kp +  0); kr[0]=t.x; kr[1]=t.y;
                t = *(const ulonglong2*)(kp +  4); kr[2]=t.x; kr[3]=t.y;
                t = *(const ulonglong2*)(kp +  8); kr[4]=t.x; kr[5]=t.y;
                t = *(const ulonglong2*)(kp + 12); kr[6]=t.x; kr[7]=t.y;
                t = *(const ulonglong2*)(vp +  0); vr[0]=t.x; vr[1]=t.y;
                t = *(const ulonglong2*)(vp +  4); vr[2]=t.x; vr[3]=t.y;
                t = *(const ulonglong2*)(vp +  8); vr[4]=t.x; vr[5]=t.y;
                t = *(const ulonglong2*)(vp + 12); vr[6]=t.x; vr[7]=t.y;
            }

            if (dr < 7) {           // pixel0: di = dr
                ull m0, m1;
                MUL2(m0, q0[0], kr[0]);
                MUL2(m1, q0[1], kr[1]);
                FMA2(m0, q0[2], kr[2]);
                FMA2(m1, q0[3], kr[3]);
                FMA2(m0, q0[4], kr[4]);
                FMA2(m1, q0[5], kr[5]);
                FMA2(m0, q0[6], kr[6]);
                FMA2(m1, q0[7], kr[7]);
                ADD2(m0, m0, m1);
                float lo, hi;
                UNPK2(lo, hi, m0);
                const float s = lo + hi + (use0 ? qe0[dr] : qe0[dj]);
                const float e = __expf(s);
                sum0 += e;
                ull ep; PACK2(ep, e, e);
#pragma unroll
                for (int j = 0; j < 8; j++) FMA2(o0[j], ep, vr[j]);
            }
            if (dr > 0) {           // pixel1: di = dr-1
                ull m0, m1;
                MUL2(m0, q1[0], kr[0]);
                MUL2(m1, q1[1], kr[1]);
                FMA2(m0, q1[2], kr[2]);
                FMA2(m1, q1[3], kr[3]);
                FMA2(m0, q1[4], kr[4]);
                FMA2(m1, q1[5], kr[5]);
                FMA2(m0, q1[6], kr[6]);
                FMA2(m1, q1[7], kr[7]);
                ADD2(m0, m0, m1);
                float lo, hi;
                UNPK2(lo, hi, m0);
                const float s = lo + hi + (use0 ? qe1[dr-1] : qe1[dj]);
                const float e = __expf(s);
                sum1 += e;
                ull ep; PACK2(ep, e, e);
#pragma unroll
                for (int j = 0; j < 8; j++) FMA2(o1[j], ep, vr[j]);
            }
        }
    }

    // ---- normalize + store both pixels ----
    const float inv0 = 1.f / sum0;
    const float inv1 = 1.f / sum1;
    float* op0 = out + (size_t)pix0 * FILTERS + h * HSIZE;
    float* op1 = out + (size_t)pix1 * FILTERS + h * HSIZE;
#pragma unroll
    for (int j = 0; j < 4; j++) {
        float a0, a1, b0, b1;
        UNPK2(a0, a1, o0[2*j]);
        UNPK2(b0, b1, o0[2*j+1]);
        float4 r0 = make_float4(a0*inv0, a1*inv0, b0*inv0, b1*inv0);
        *(float4*)(op0 + j*4) = r0;
        UNPK2(a0, a1, o1[2*j]);
        UNPK2(b0, b1, o1[2*j+1]);
        float4 r1 = make_float4(a0*inv1, a1*inv1, b0*inv1, b1*inv1);
        *(float4*)(op1 + j*4) = r1;
    }
}

// ---------------------------------------------------------------------------
extern "C" void kernel_launch(void* const* d_in, const int* in_sizes, int n_in,
                              void* d_out, int out_size)
{
    const float* x    = (const float*)d_in[0];
    const float* Wq   = (const float*)d_in[1];
    const float* bq   = (const float*)d_in[2];
    const float* Wk   = (const float*)d_in[3];
    const float* bk   = (const float*)d_in[4];
    const float* Wv   = (const float*)d_in[5];
    const float* bv   = (const float*)d_in[6];
    const float* emb0 = (const float*)d_in[7];
    const float* emb1 = (const float*)d_in[8];
    float* out = (float*)d_out;

    float* qkv = nullptr;
    cudaGetSymbolAddress((void**)&qkv, g_QKV);

    cudaFuncSetAttribute(attn_kernel,
                         cudaFuncAttributeMaxDynamicSharedMemorySize, ATTN_SMEM);

    dim3 gg(NPIX / GBM, NQKV / GBN);   // (128, 6)
    qkv_gemm_kernel<<<gg, 256>>>(x, Wq, bq, Wk, bk, Wv, bv, qkv);

    dim3 ga(16, BATCH, HEADS);         // 512 blocks
    attn_kernel<<<ga, 128, ATTN_SMEM>>>(qkv, emb0, emb1, out);
}